// round 4
// baseline (speedup 1.0000x reference)
#include <cuda_runtime.h>
#include <cuda_fp16.h>
#include <stdint.h>
#include <math.h>

#define N_TOK  32768
#define HID    1024
#define NEXP   64
#define H4     256
#define N_TOT  320          // 64 router + 256 hidden

#define MT      128         // M rows per CTA
#define KC      32          // K per chunk
#define NCHUNK  (HID / KC)  // 32
#define THREADS 512

// smem layout (bytes)
#define STB      40960                  // per B stage (hi 20480 + lo 20480)
#define B_BASE   0
#define A32B     81920                  // fp32 A stages
#define A32ST    16384
#define A16B     114688                 // f16 A stages (hi 8192 + lo 8192)
#define A16ST    16384
#define SMEM_TOTAL 147456

// ---------------- device scratch ----------------
__device__ __align__(16) __half g_whi[N_TOT * HID];
__device__ __align__(16) __half g_wlo[N_TOT * HID];
__device__ float g_load[NEXP];
__device__ float g_ent;

__device__ __forceinline__ uint32_t smem_u32(const void* p) {
    uint32_t a;
    asm("{ .reg .u64 t; cvta.to.shared.u64 t, %1; cvt.u32.u64 %0, t; }" : "=r"(a) : "l"(p));
    return a;
}
__device__ __forceinline__ void cp16(uint32_t dst, const void* src) {
    asm volatile("cp.async.cg.shared.global [%0], [%1], 16;"
                 :: "r"(dst), "l"(__cvta_generic_to_global(src)));
}
__device__ __forceinline__ void ldsm4(uint32_t* r, uint32_t addr) {
    asm volatile("ldmatrix.sync.aligned.m8n8.x4.shared.b16 {%0,%1,%2,%3}, [%4];"
                 : "=r"(r[0]), "=r"(r[1]), "=r"(r[2]), "=r"(r[3]) : "r"(addr));
}
__device__ __forceinline__ void mma16816(float* c, const uint32_t* a, const uint32_t* b) {
    asm volatile(
        "mma.sync.aligned.m16n8k16.row.col.f32.f16.f16.f32 "
        "{%0,%1,%2,%3}, {%4,%5,%6,%7}, {%8,%9}, {%0,%1,%2,%3};"
        : "+f"(c[0]), "+f"(c[1]), "+f"(c[2]), "+f"(c[3])
        : "r"(a[0]), "r"(a[1]), "r"(a[2]), "r"(a[3]), "r"(b[0]), "r"(b[1]));
}
__device__ __forceinline__ uint32_t h2u(__half2 h) {
    uint32_t u; __builtin_memcpy(&u, &h, 4); return u;
}

// ---------------- prep: fp32 weights -> fp16 hi/lo ----------------
__global__ void prep_w_kernel(const float* __restrict__ RW, const float* __restrict__ W1) {
    int i = blockIdx.x * blockDim.x + threadIdx.x;
    if (i >= N_TOT * HID) return;
    int row = i >> 10;
    float v = (row < NEXP) ? RW[i] : W1[i - NEXP * HID];
    __half h = __float2half_rn(v);
    g_whi[i] = h;
    g_wlo[i] = __float2half_rn(v - __half2float(h));
}

__global__ void init_kernel() {
    int i = threadIdx.x;
    if (i < NEXP) g_load[i] = 0.0f;
    if (i == 0)   g_ent = 0.0f;
}

// ---------------- fused GEMM + router epilogue ----------------
__global__ void __launch_bounds__(THREADS, 1)
gemm_kernel(const float* __restrict__ X,
            const float* __restrict__ B1, const float* __restrict__ W2,
            const float* __restrict__ B2,
            float* __restrict__ logits, float* __restrict__ sel, float* __restrict__ wts)
{
    extern __shared__ __align__(1024) char smem[];
    const uint32_t sbase = smem_u32(smem);
    const int tid = threadIdx.x;
    const int lane = tid & 31;
    const int wid = tid >> 5;
    const int wm = wid & 3;
    const int wn = wid >> 2;
    const int m0 = blockIdx.x * MT;

    float acc[2][10][4];
#pragma unroll
    for (int i = 0; i < 2; i++)
#pragma unroll
        for (int j = 0; j < 10; j++)
#pragma unroll
            for (int r = 0; r < 4; r++) acc[i][j][r] = 0.0f;

    // ldmatrix address precompute (64B rows, SW64)
    uint32_t aOff[2], aXor[2];
#pragma unroll
    for (int mt = 0; mt < 2; mt++) {
        int row = wm * 32 + mt * 16 + (lane & 15);
        aOff[mt] = (uint32_t)row * 64;
        aXor[mt] = ((uint32_t)row * 8) & 0x30;
    }
    const uint32_t aKB = ((lane >> 4) & 1) * 16;
    uint32_t bOff[5], bXor[5];
#pragma unroll
    for (int p = 0; p < 5; p++) {
        int n = wn * 80 + (p * 2 + ((lane >> 4) & 1)) * 8 + (lane & 7);
        bOff[p] = (uint32_t)n * 64;
        bXor[p] = ((uint32_t)n * 8) & 0x30;
    }
    const uint32_t bKB = ((lane >> 3) & 1) * 16;

    // ---- async loaders ----
    // B unit j in [0,2560): v=hi/lo, row n, granule g (16B)
    auto bUnit = [&](int j, int cB) {
        int v = j >= 1280;
        int jj = v ? j - 1280 : j;
        int n = jj >> 2, g = jj & 3;
        const __half* src = (v ? g_wlo : g_whi) + (size_t)n * HID + cB * KC + g * 8;
        uint32_t dst = sbase + B_BASE + (cB & 1) * STB + v * 20480 +
                       (((uint32_t)n * 64 + g * 16) ^ (((uint32_t)n * 8) & 0x30));
        cp16(dst, src);
    };
    // A32 unit q in [0,1024): row, granule g (16B of fp32)
    auto aUnit = [&](int q, int cA) {
        int row = q >> 3, g = q & 7;
        const float* src = X + (size_t)(m0 + row) * HID + cA * KC + g * 4;
        uint32_t dst = sbase + A32B + (cA & 1) * A32ST +
                       (((uint32_t)row * 128 + g * 16) ^ (((uint32_t)row * 16) & 0x70));
        cp16(dst, src);
    };

    // converter: A32 stage (cc&1) -> A16 stage (cc&1)
    auto convert = [&](int cc) {
        const int s = cc & 1;
        const uint32_t a32 = sbase + A32B + s * A32ST;
        const uint32_t a16 = sbase + A16B + s * A16ST;
        int row = tid >> 2, cq = tid & 3;
        uint32_t xr = ((uint32_t)row * 16) & 0x70;
        uint32_t base = a32 + (uint32_t)row * 128;
        float4 f0 = *reinterpret_cast<const float4*>(smem + (base + ((cq * 32) ^ xr) - sbase));
        float4 f1 = *reinterpret_cast<const float4*>(smem + (base + ((cq * 32 + 16) ^ xr) - sbase));
        __half2 h0 = __floats2half2_rn(f0.x, f0.y);
        __half2 h1 = __floats2half2_rn(f0.z, f0.w);
        __half2 h2 = __floats2half2_rn(f1.x, f1.y);
        __half2 h3 = __floats2half2_rn(f1.z, f1.w);
        float2 g0 = __half22float2(h0), g1 = __half22float2(h1);
        float2 g2 = __half22float2(h2), g3 = __half22float2(h3);
        __half2 l0 = __floats2half2_rn(f0.x - g0.x, f0.y - g0.y);
        __half2 l1 = __floats2half2_rn(f0.z - g1.x, f0.w - g1.y);
        __half2 l2 = __floats2half2_rn(f1.x - g2.x, f1.y - g2.y);
        __half2 l3 = __floats2half2_rn(f1.z - g3.x, f1.w - g3.y);
        uint32_t doff = (uint32_t)row * 64 + (((uint32_t)cq * 16) ^ (((uint32_t)row * 8) & 0x30));
        *reinterpret_cast<uint4*>(smem + (a16 - sbase) + doff) =
            make_uint4(h2u(h0), h2u(h1), h2u(h2), h2u(h3));
        *reinterpret_cast<uint4*>(smem + (a16 - sbase) + 8192 + doff) =
            make_uint4(h2u(l0), h2u(l1), h2u(l2), h2u(l3));
    };

    // ---- prologue: B(0), A32(0), A32(1) in one group ----
#pragma unroll
    for (int it = 0; it < 9; it++) {
        int u = tid + it * THREADS;
        if (u < 2560) bUnit(u, 0);
        else if (u < 3584) aUnit(u - 2560, 0);
        else aUnit(u - 3584, 1);
    }
    asm volatile("cp.async.commit_group;");
    asm volatile("cp.async.wait_group 0;");
    __syncthreads();
    convert(0);
    __syncthreads();

    // ---- mainloop ----
    for (int c = 0; c < NCHUNK; c++) {
        // issue G_c = [B(c+1), A32(c+2)]
        const bool doB = (c + 1 < NCHUNK), doA = (c + 2 < NCHUNK);
#pragma unroll
        for (int it = 0; it < 7; it++) {
            int u = tid + it * THREADS;
            if (u < 2560) { if (doB) bUnit(u, c + 1); }
            else          { if (doA) aUnit(u - 2560, c + 2); }
        }
        asm volatile("cp.async.commit_group;");
        asm volatile("cp.async.wait_group 1;");
        __syncthreads();

        if (c + 1 < NCHUNK) convert(c + 1);

        const uint32_t aHi = sbase + A16B + (c & 1) * A16ST;
        const uint32_t bHi = sbase + B_BASE + (c & 1) * STB;
#pragma unroll
        for (int ks = 0; ks < 2; ks++) {
            const uint32_t kb = ks * 32;
            uint32_t ah[2][4], al[2][4], bb[5][4];
#pragma unroll
            for (int mt = 0; mt < 2; mt++)
                ldsm4(ah[mt], aHi + aOff[mt] + ((kb + aKB) ^ aXor[mt]));
#pragma unroll
            for (int p = 0; p < 5; p++)
                ldsm4(bb[p], bHi + bOff[p] + ((kb + bKB) ^ bXor[p]));
#pragma unroll
            for (int mt = 0; mt < 2; mt++)
#pragma unroll
                for (int p = 0; p < 5; p++) {
                    mma16816(acc[mt][p * 2 + 0], ah[mt], &bb[p][0]);
                    mma16816(acc[mt][p * 2 + 1], ah[mt], &bb[p][2]);
                }
#pragma unroll
            for (int mt = 0; mt < 2; mt++)
                ldsm4(al[mt], aHi + 8192 + aOff[mt] + ((kb + aKB) ^ aXor[mt]));
#pragma unroll
            for (int mt = 0; mt < 2; mt++)
#pragma unroll
                for (int p = 0; p < 5; p++) {
                    mma16816(acc[mt][p * 2 + 0], al[mt], &bb[p][0]);
                    mma16816(acc[mt][p * 2 + 1], al[mt], &bb[p][2]);
                }
#pragma unroll
            for (int p = 0; p < 5; p++)
                ldsm4(bb[p], bHi + 20480 + bOff[p] + ((kb + bKB) ^ bXor[p]));
#pragma unroll
            for (int mt = 0; mt < 2; mt++)
#pragma unroll
                for (int p = 0; p < 5; p++) {
                    mma16816(acc[mt][p * 2 + 0], ah[mt], &bb[p][0]);
                    mma16816(acc[mt][p * 2 + 1], ah[mt], &bb[p][2]);
                }
        }
        __syncthreads();
    }

    // ---------------- fused epilogue ----------------
    float* s_log  = reinterpret_cast<float*>(smem);           // [128][68]
    float* s_u    = reinterpret_cast<float*>(smem + 34816);   // [128]
    float* s_load = s_u + 128;                                // [64]
    float* s_ent  = s_load + NEXP;                            // [1]

    if (tid < MT)   s_u[tid] = B2[0];
    if (tid < NEXP) s_load[tid] = 0.0f;
    if (tid == 0)   *s_ent = 0.0f;
    __syncthreads();

#pragma unroll
    for (int mt = 0; mt < 2; mt++) {
        float u0 = 0.0f, u1 = 0.0f;
        const int row0 = wm * 32 + mt * 16 + (lane >> 2);
#pragma unroll
        for (int nt = 0; nt < 10; nt++) {
            const int nb = wn * 80 + nt * 8 + (lane & 3) * 2;
            const bool is_logit = (wn == 0 && nt < 8);
#pragma unroll
            for (int r = 0; r < 4; r++) {
                const int n = nb + (r & 1);
                const float v = acc[mt][nt][r];
                if (is_logit) {
                    const int rl = row0 + ((r >= 2) ? 8 : 0);
                    s_log[rl * 68 + n] = v;
                } else {
                    const int h = n - 64;
                    const float hh = fmaxf(v + __ldg(B1 + h), 0.0f) * __ldg(W2 + h);
                    if (r < 2) u0 += hh; else u1 += hh;
                }
            }
        }
        u0 += __shfl_xor_sync(0xffffffffu, u0, 1);
        u0 += __shfl_xor_sync(0xffffffffu, u0, 2);
        u1 += __shfl_xor_sync(0xffffffffu, u1, 1);
        u1 += __shfl_xor_sync(0xffffffffu, u1, 2);
        if ((lane & 3) == 0) {
            atomicAdd(&s_u[row0], u0);
            atomicAdd(&s_u[row0 + 8], u1);
        }
    }
    __syncthreads();

    if (tid < MT) {
        // per-token top-k / softmax / stats (token = tid)
        const int m = m0 + tid;
        const float* row = s_log + tid * 68;

        float v0 = -INFINITY, v1 = -INFINITY, v2 = -INFINITY, v3 = -INFINITY;
        int i0 = 0, i1 = 0, i2 = 0, i3 = 0;
#pragma unroll
        for (int j = 0; j < NEXP; j++) {
            float x = row[j];
            if (x > v3) {
                if (x > v0)      { v3=v2;i3=i2; v2=v1;i2=i1; v1=v0;i1=i0; v0=x;i0=j; }
                else if (x > v1) { v3=v2;i3=i2; v2=v1;i2=i1; v1=x;i1=j; }
                else if (x > v2) { v3=v2;i3=i2; v2=x;i2=j; }
                else             { v3=x;i3=j; }
            }
        }
        float ex[NEXP];
        float se = 0.0f;
#pragma unroll
        for (int j = 0; j < NEXP; j++) { ex[j] = __expf(row[j] - v0); se += ex[j]; }
        float inv = 1.0f / se;
        float ent = 0.0f;
#pragma unroll
        for (int jj = 0; jj < NEXP; jj++) {
            int e = (jj + tid) & 63;
            float p = ex[e] * inv;
            ent -= p * __logf(p + 1e-8f);
            atomicAdd(&s_load[e], p);
        }
        atomicAdd(s_ent, ent);

        float u = s_u[tid];
        float cplx = 1.0f / (1.0f + expf(-u));
        int kk = (cplx > 0.5f) ? 4 : 1;
        float e0 = 1.0f;
        float e1 = (kk > 1) ? expf(v1 - v0) : 0.0f;
        float e2 = (kk > 2) ? expf(v2 - v0) : 0.0f;
        float e3 = (kk > 3) ? expf(v3 - v0) : 0.0f;
        float wi = 1.0f / (e0 + e1 + e2 + e3);

        *reinterpret_cast<float4*>(sel + (size_t)m * 4) =
            make_float4((float)i0, (float)((kk > 1) ? i1 : 0),
                        (float)((kk > 2) ? i2 : 0), (float)((kk > 3) ? i3 : 0));
        *reinterpret_cast<float4*>(wts + (size_t)m * 4) =
            make_float4(e0 * wi, e1 * wi, e2 * wi, e3 * wi);
    } else {
        // warps 4-15: coalesced logits store (2048 float4)
        for (int t = tid - MT; t < MT * 16; t += (THREADS - MT)) {
            int r = t >> 4, c4 = t & 15;
            float4 v = *reinterpret_cast<const float4*>(s_log + r * 68 + c4 * 4);
            *reinterpret_cast<float4*>(logits + (size_t)(m0 + r) * NEXP + c4 * 4) = v;
        }
    }
    __syncthreads();

    if (tid < NEXP) atomicAdd(&g_load[tid], s_load[tid]);
    if (tid == 0)   atomicAdd(&g_ent, *s_ent);
}

// ---------------- finalize ----------------
__global__ void finalize_kernel(float* __restrict__ out_var, float* __restrict__ out_ent) {
    if (threadIdx.x == 0) {
        float xs[NEXP];
        float mean = 0.0f;
        for (int e = 0; e < NEXP; e++) { xs[e] = g_load[e] * (1.0f / N_TOK); mean += xs[e]; }
        mean *= (1.0f / NEXP);
        float var = 0.0f;
        for (int e = 0; e < NEXP; e++) { float d = xs[e] - mean; var += d * d; }
        out_var[0] = var * (1.0f / (NEXP - 1));
        out_ent[0] = g_ent * (1.0f / N_TOK);
    }
}

// ---------------- launch ----------------
extern "C" void kernel_launch(void* const* d_in, const int* in_sizes, int n_in,
                              void* d_out, int out_size) {
    const float* X  = (const float*)d_in[0];
    const float* RW = (const float*)d_in[1];
    const float* W1 = (const float*)d_in[2];
    const float* B1 = (const float*)d_in[3];
    const float* W2 = (const float*)d_in[4];
    const float* B2 = (const float*)d_in[5];

    float* out    = (float*)d_out;
    float* logits = out;
    float* sel    = logits + (size_t)N_TOK * NEXP;
    float* wts    = sel + (size_t)N_TOK * 4;
    float* ovar   = wts + (size_t)N_TOK * 4;
    float* oent   = ovar + 1;

    cudaFuncSetAttribute(gemm_kernel, cudaFuncAttributeMaxDynamicSharedMemorySize, SMEM_TOTAL);

    prep_w_kernel<<<(N_TOT * HID + 255) / 256, 256>>>(RW, W1);
    init_kernel<<<1, 64>>>();
    gemm_kernel<<<N_TOK / MT, THREADS, SMEM_TOTAL>>>(X, B1, W2, B2, logits, sel, wts);
    finalize_kernel<<<1, 32>>>(ovar, oent);
}